// round 2
// baseline (speedup 1.0000x reference)
#include <cuda_runtime.h>
#include <math.h>
#include <stdint.h>

#define B_    64
#define CIN   96
#define CMID  576
#define COUT  96
#define HW_   784
#define NPIX  (B_*HW_)      // 50176
#define NBITF 127.0f

// ---------------- device scratch (no allocations allowed) ----------------
__device__ float g_s[4];                       // s0..s3
__device__ float g_ws1[CMID], g_bf1[CMID];
__device__ float g_ws2[CMID], g_bf2[CMID];
__device__ float g_ws3[COUT], g_bf3[COUT];
__device__ __align__(16) int g_w1p[24 * CMID];             // [k_packed][co], 4 int8/word
__device__ __align__(16) int g_w2p[CMID * 3];              // [co][row], 3 int8/word (k0,k1,k2)
__device__ __align__(16) int g_w3p[144 * COUT];            // [k_packed][co]
__device__ __align__(16) signed char g_y1[B_ * CMID * HW_];  // stage-1 int8 activations
__device__ __align__(16) signed char g_y2[B_ * CMID * HW_];  // stage-2 int8 activations

// ---------------- prep: scales ----------------
__global__ void prep_scales(const float* __restrict__ r0, const float* __restrict__ r1,
                            const float* __restrict__ r2, const float* __restrict__ r3,
                            const int* __restrict__ cl, float* s3out) {
    int c = cl[0];
    g_s[0] = r0[c] / NBITF;
    g_s[1] = r1[c] / NBITF;
    g_s[2] = r2[c] / NBITF;
    float s3 = r3[c] / NBITF;
    g_s[3] = s3;
    if (s3out) *s3out = s3;
}

// ---------------- prep: BN fold + weight quant + packing ----------------
__global__ void __launch_bounds__(128) prep_weights(
    const float* __restrict__ w1, const float* __restrict__ g1, const float* __restrict__ b1,
    const float* __restrict__ m1, const float* __restrict__ v1,
    const float* __restrict__ w2, const float* __restrict__ g2, const float* __restrict__ b2,
    const float* __restrict__ m2, const float* __restrict__ v2,
    const float* __restrict__ w3, const float* __restrict__ g3, const float* __restrict__ b3,
    const float* __restrict__ m3, const float* __restrict__ v3) {
    __shared__ float sv[CMID];
    __shared__ signed char qs[CMID];
    __shared__ float red[128];
    int t = threadIdx.x;
    int bid = blockIdx.x;

    if (bid < CMID) {
        // ----- w1: [576, 96] -----
        int co = bid;
        float scale = g1[co] / sqrtf(v1[co] + 1e-5f);
        float v = 0.f;
        if (t < CIN) { v = w1[co * CIN + t] * scale; sv[t] = v; }
        red[t] = (t < CIN) ? fabsf(v) : 0.f;
        __syncthreads();
        for (int s = 64; s > 0; s >>= 1) { if (t < s) red[t] = fmaxf(red[t], red[t + s]); __syncthreads(); }
        float sc = red[0] / NBITF;
        if (t == 0) { g_ws1[co] = sc; g_bf1[co] = b1[co] - m1[co] * scale; }
        if (t < CIN) {
            float q = rintf(sv[t] / sc);
            q = fminf(fmaxf(q, -127.f), 127.f);
            qs[t] = (signed char)q;
        }
        __syncthreads();
        if (t < 24) {
            int w = (qs[4*t] & 0xFF) | ((qs[4*t+1] & 0xFF) << 8) |
                    ((qs[4*t+2] & 0xFF) << 16) | ((qs[4*t+3] & 0xFF) << 24);
            g_w1p[t * CMID + co] = w;
        }
    } else if (bid < 2 * CMID) {
        // ----- w2: [576, 9] depthwise -----
        int co = bid - CMID;
        float scale = g2[co] / sqrtf(v2[co] + 1e-5f);
        float v = 0.f;
        if (t < 9) { v = w2[co * 9 + t] * scale; sv[t] = v; }
        red[t] = (t < 9) ? fabsf(v) : 0.f;
        __syncthreads();
        for (int s = 64; s > 0; s >>= 1) { if (t < s) red[t] = fmaxf(red[t], red[t + s]); __syncthreads(); }
        float sc = red[0] / NBITF;
        if (t == 0) { g_ws2[co] = sc; g_bf2[co] = b2[co] - m2[co] * scale; }
        if (t < 9) {
            float q = rintf(sv[t] / sc);
            q = fminf(fmaxf(q, -127.f), 127.f);
            qs[t] = (signed char)q;
        }
        __syncthreads();
        if (t < 3) {
            int w = (qs[3*t] & 0xFF) | ((qs[3*t+1] & 0xFF) << 8) | ((qs[3*t+2] & 0xFF) << 16);
            g_w2p[co * 3 + t] = w;
        }
    } else {
        // ----- w3: [96, 576] -----
        int co = bid - 2 * CMID;
        float scale = g3[co] / sqrtf(v3[co] + 1e-5f);
        float lm = 0.f;
        for (int k = t; k < CMID; k += 128) {
            float v = w3[co * CMID + k] * scale;
            sv[k] = v;
            lm = fmaxf(lm, fabsf(v));
        }
        red[t] = lm;
        __syncthreads();
        for (int s = 64; s > 0; s >>= 1) { if (t < s) red[t] = fmaxf(red[t], red[t + s]); __syncthreads(); }
        float sc = red[0] / NBITF;
        if (t == 0) { g_ws3[co] = sc; g_bf3[co] = b3[co] - m3[co] * scale; }
        for (int k = t; k < CMID; k += 128) {
            float q = rintf(sv[k] / sc);
            q = fminf(fmaxf(q, -127.f), 127.f);
            qs[k] = (signed char)q;
        }
        __syncthreads();
        // FIX (R1): 144 pack words but only 128 threads — must stride, else
        // input channels 512..575 of conv3 are silently zero.
        for (int p = t; p < 144; p += 128) {
            int w = (qs[4*p] & 0xFF) | ((qs[4*p+1] & 0xFF) << 8) |
                    ((qs[4*p+2] & 0xFF) << 16) | ((qs[4*p+3] & 0xFF) << 24);
            g_w3p[p * COUT + co] = w;
        }
    }
}

// ---------------- k1: quant(x) + 1x1 conv (96->576) + ReLU6 + requant -> int8 ----------------
__global__ void __launch_bounds__(256) k1_conv1(const float* __restrict__ x) {
    __shared__ __align__(16) int a_sm[24][128];   // packed int8 activations [k][px]
    __shared__ int w_sm[24][192];                 // weight chunk [k][co_local]
    const int tid = threadIdx.x;
    const int n0 = blockIdx.x * 128;

    const float s0 = g_s[0];
    const float inv_s0 = 1.0f / s0;
    const float s1 = g_s[1];
    const float inv_s1 = 1.0f / s1;

    // load + quantize x tile into packed smem
    signed char* a_bytes = (signed char*)a_sm;
    for (int idx = tid; idx < CIN * 128; idx += 256) {
        int c = idx >> 7;
        int px = idx & 127;
        int n = n0 + px;
        int b = n / HW_;
        int hw = n - b * HW_;
        float v = x[(b * CIN + c) * HW_ + hw];
        float q = rintf(v * inv_s0);
        q = fminf(fmaxf(q, -127.f), 127.f);
        a_bytes[((c >> 2) * 128 + px) * 4 + (c & 3)] = (signed char)q;
    }

    const int pg = tid & 15;
    const int lane = tid >> 4;
    const int px0 = pg * 8;
    const int n = n0 + px0;
    const int b = n / HW_;
    const int hw = n - b * HW_;   // multiple of 8, octet never crosses image boundary

    __syncthreads();

    for (int chunk = 0; chunk < 3; ++chunk) {
        int co_base = chunk * 192;
        if (chunk) __syncthreads();
        for (int idx = tid; idx < 24 * 192; idx += 256) {
            int k = idx / 192;
            int c = idx - k * 192;
            w_sm[k][c] = g_w1p[k * CMID + co_base + c];
        }
        __syncthreads();

        #pragma unroll
        for (int half = 0; half < 2; ++half) {
            int acc[6][8];
            #pragma unroll
            for (int i = 0; i < 6; ++i)
                #pragma unroll
                for (int j = 0; j < 8; ++j) acc[i][j] = 0;

            #pragma unroll 4
            for (int k = 0; k < 24; ++k) {
                int4 a0 = *(const int4*)&a_sm[k][px0];
                int4 a1 = *(const int4*)&a_sm[k][px0 + 4];
                #pragma unroll
                for (int i = 0; i < 6; ++i) {
                    int w = w_sm[k][(half * 6 + i) * 16 + lane];
                    acc[i][0] = __dp4a(a0.x, w, acc[i][0]);
                    acc[i][1] = __dp4a(a0.y, w, acc[i][1]);
                    acc[i][2] = __dp4a(a0.z, w, acc[i][2]);
                    acc[i][3] = __dp4a(a0.w, w, acc[i][3]);
                    acc[i][4] = __dp4a(a1.x, w, acc[i][4]);
                    acc[i][5] = __dp4a(a1.y, w, acc[i][5]);
                    acc[i][6] = __dp4a(a1.z, w, acc[i][6]);
                    acc[i][7] = __dp4a(a1.w, w, acc[i][7]);
                }
            }

            #pragma unroll
            for (int i = 0; i < 6; ++i) {
                int co = co_base + (half * 6 + i) * 16 + lane;
                float al = s0 * g_ws1[co];
                float bb = g_bf1[co];
                unsigned int lo = 0, hi = 0;
                #pragma unroll
                for (int j = 0; j < 8; ++j) {
                    float y = (float)acc[i][j] * al + bb;
                    y = fminf(fmaxf(y, 0.f), 6.f);
                    int q = (int)rintf(y * inv_s1);
                    q = q > 127 ? 127 : q;
                    if (j < 4) lo |= (unsigned)(q & 0xFF) << (8 * j);
                    else       hi |= (unsigned)(q & 0xFF) << (8 * (j - 4));
                }
                *(uint2*)(g_y1 + (b * CMID + co) * HW_ + hw) = make_uint2(lo, hi);
            }
        }
    }
}

// ---------------- k2: depthwise 3x3 (int8) + ReLU6 + requant -> int8 ----------------
__global__ void __launch_bounds__(256) k2_dw() {
    int t = blockIdx.x * 256 + threadIdx.x;           // one thread per (b, c, h) row
    if (t >= B_ * CMID * 28) return;
    int h = t % 28;
    int bc = t / 28;
    int c = bc % CMID;
    int b = bc / CMID;
    int base = (b * CMID + c) * HW_;

    int r0[8], r1[8], r2[8];
    const int* p1 = (const int*)(g_y1 + base + h * 28);
    #pragma unroll
    for (int q = 0; q < 7; ++q) r1[q] = p1[q];
    r1[7] = 0;
    if (h > 0) {
        const int* p0 = p1 - 7;
        #pragma unroll
        for (int q = 0; q < 7; ++q) r0[q] = p0[q];
    } else {
        #pragma unroll
        for (int q = 0; q < 7; ++q) r0[q] = 0;
    }
    r0[7] = 0;
    if (h < 27) {
        const int* p2 = p1 + 7;
        #pragma unroll
        for (int q = 0; q < 7; ++q) r2[q] = p2[q];
    } else {
        #pragma unroll
        for (int q = 0; q < 7; ++q) r2[q] = 0;
    }
    r2[7] = 0;

    int wp0 = g_w2p[c * 3 + 0];
    int wp1 = g_w2p[c * 3 + 1];
    int wp2 = g_w2p[c * 3 + 2];
    float al = g_s[1] * g_ws2[c];
    float bb = g_bf2[c];
    float inv_s2 = 1.0f / g_s[2];

    unsigned int ow[7];
    #pragma unroll
    for (int q = 0; q < 7; ++q) ow[q] = 0u;

    #pragma unroll
    for (int w = 0; w < 28; ++w) {
        int op0, op1, op2;
        if (w == 0) {
            // bytes: (0, b0, b1, dontcare) — byte3 weight is 0
            op0 = __byte_perm(r0[0], 0, 0x2104);
            op1 = __byte_perm(r1[0], 0, 0x2104);
            op2 = __byte_perm(r2[0], 0, 0x2104);
        } else {
            int s = w - 1, q = s >> 2, o = s & 3;
            unsigned sel = 0x3210u + (unsigned)o * 0x1111u;
            op0 = __byte_perm(r0[q], r0[q + 1], sel);
            op1 = __byte_perm(r1[q], r1[q + 1], sel);
            op2 = __byte_perm(r2[q], r2[q + 1], sel);
        }
        int acc = __dp4a(op0, wp0, __dp4a(op1, wp1, __dp4a(op2, wp2, 0)));
        float y = (float)acc * al + bb;
        y = fminf(fmaxf(y, 0.f), 6.f);
        int qv = (int)rintf(y * inv_s2);
        qv = qv > 127 ? 127 : qv;
        ow[w >> 2] |= (unsigned)(qv & 0xFF) << (8 * (w & 3));
    }
    int* po = (int*)(g_y2 + base + h * 28);
    #pragma unroll
    for (int q = 0; q < 7; ++q) po[q] = (int)ow[q];
}

// ---------------- k3: 1x1 conv (576->96) + bias + residual + final quant -> fp32 ----------------
__global__ void __launch_bounds__(256) k3_conv3(const float* __restrict__ x,
                                                float* __restrict__ out) {
    __shared__ __align__(16) int a_sm[48][128];   // 192-channel chunk packed [k][px]
    __shared__ int w_sm[48][96];
    const int tid = threadIdx.x;
    const int n0 = blockIdx.x * 128;
    const int pg = tid & 15;
    const int lane = tid >> 4;
    const int px0 = pg * 8;

    int acc[6][8];
    #pragma unroll
    for (int i = 0; i < 6; ++i)
        #pragma unroll
        for (int j = 0; j < 8; ++j) acc[i][j] = 0;

    signed char* a_bytes = (signed char*)a_sm;

    for (int kc = 0; kc < 3; ++kc) {
        if (kc) __syncthreads();
        // load 192 int8 channels for 128 px, scatter-pack into dp4a words
        for (int idx = tid; idx < 192 * 32; idx += 256) {
            int cl = idx >> 5;
            int quad = idx & 31;
            int px = quad * 4;
            int c = kc * 192 + cl;
            int nn = n0 + px;
            int bb_ = nn / HW_;
            int hw_ = nn - bb_ * HW_;
            int v = *(const int*)(g_y2 + (bb_ * CMID + c) * HW_ + hw_);
            int k = cl >> 2;
            int byt = cl & 3;
            #pragma unroll
            for (int j = 0; j < 4; ++j)
                a_bytes[(k * 128 + px + j) * 4 + byt] = (signed char)((v >> (8 * j)) & 0xFF);
        }
        for (int idx = tid; idx < 48 * 96; idx += 256) {
            int k = idx / 96;
            int c = idx - k * 96;
            w_sm[k][c] = g_w3p[(kc * 48 + k) * COUT + c];
        }
        __syncthreads();

        #pragma unroll 4
        for (int k = 0; k < 48; ++k) {
            int4 a0 = *(const int4*)&a_sm[k][px0];
            int4 a1 = *(const int4*)&a_sm[k][px0 + 4];
            #pragma unroll
            for (int i = 0; i < 6; ++i) {
                int w = w_sm[k][i * 16 + lane];
                acc[i][0] = __dp4a(a0.x, w, acc[i][0]);
                acc[i][1] = __dp4a(a0.y, w, acc[i][1]);
                acc[i][2] = __dp4a(a0.z, w, acc[i][2]);
                acc[i][3] = __dp4a(a0.w, w, acc[i][3]);
                acc[i][4] = __dp4a(a1.x, w, acc[i][4]);
                acc[i][5] = __dp4a(a1.y, w, acc[i][5]);
                acc[i][6] = __dp4a(a1.z, w, acc[i][6]);
                acc[i][7] = __dp4a(a1.w, w, acc[i][7]);
            }
        }
    }

    const float s2 = g_s[2];
    const float s3 = g_s[3];
    const float inv_s3 = 1.0f / s3;
    int n = n0 + px0;
    int b = n / HW_;
    int hw = n - b * HW_;

    #pragma unroll
    for (int i = 0; i < 6; ++i) {
        int co = i * 16 + lane;
        float al = s2 * g_ws3[co];
        float bb = g_bf3[co];
        int off = (b * COUT + co) * HW_ + hw;
        float4 x0 = *(const float4*)(x + off);
        float4 x1 = *(const float4*)(x + off + 4);
        float xv[8] = {x0.x, x0.y, x0.z, x0.w, x1.x, x1.y, x1.z, x1.w};
        float o[8];
        #pragma unroll
        for (int j = 0; j < 8; ++j) {
            float y = (float)acc[i][j] * al + bb + xv[j];
            float q = rintf(y * inv_s3);
            q = fminf(fmaxf(q, -127.f), 127.f);
            o[j] = q * s3;
        }
        *(float4*)(out + off) = make_float4(o[0], o[1], o[2], o[3]);
        *(float4*)(out + off + 4) = make_float4(o[4], o[5], o[6], o[7]);
    }
}

// ---------------- launch ----------------
extern "C" void kernel_launch(void* const* d_in, const int* in_sizes, int n_in,
                              void* d_out, int out_size) {
    const float* x  = (const float*)d_in[0];
    const float* w1 = (const float*)d_in[1];
    const float* g1 = (const float*)d_in[2];
    const float* b1 = (const float*)d_in[3];
    const float* m1 = (const float*)d_in[4];
    const float* v1 = (const float*)d_in[5];
    const float* w2 = (const float*)d_in[6];
    const float* g2 = (const float*)d_in[7];
    const float* b2 = (const float*)d_in[8];
    const float* m2 = (const float*)d_in[9];
    const float* v2 = (const float*)d_in[10];
    const float* w3 = (const float*)d_in[11];
    const float* g3 = (const float*)d_in[12];
    const float* b3 = (const float*)d_in[13];
    const float* m3 = (const float*)d_in[14];
    const float* v3 = (const float*)d_in[15];
    const float* r0 = (const float*)d_in[16];
    const float* r1 = (const float*)d_in[17];
    const float* r2 = (const float*)d_in[18];
    const float* r3 = (const float*)d_in[19];
    const int*   cl = (const int*)d_in[20];

    float* out = (float*)d_out;
    const int NOUT = B_ * COUT * HW_;   // 4,816,896
    float* s3out = (out_size > NOUT) ? out + NOUT : nullptr;

    prep_scales<<<1, 1>>>(r0, r1, r2, r3, cl, s3out);
    prep_weights<<<2 * CMID + COUT, 128>>>(w1, g1, b1, m1, v1,
                                           w2, g2, b2, m2, v2,
                                           w3, g3, b3, m3, v3);
    k1_conv1<<<NPIX / 128, 256>>>(x);
    k2_dw<<<(B_ * CMID * 28 + 255) / 256, 256>>>();
    k3_conv3<<<NPIX / 128, 256>>>(x, out);
}

// round 3
// speedup vs baseline: 1.3408x; 1.3408x over previous
#include <cuda_runtime.h>
#include <math.h>
#include <stdint.h>

#define B_    64
#define CIN   96
#define CMID  576
#define COUT  96
#define HW_   784
#define NPIX  (B_*HW_)      // 50176
#define NBITF 127.0f

// ---------------- device scratch (no allocations allowed) ----------------
__device__ float g_s[4];                       // s0..s3
__device__ float g_ws1[CMID], g_bf1[CMID];
__device__ float g_ws2[CMID], g_bf2[CMID];
__device__ float g_ws3[COUT], g_bf3[COUT];
__device__ __align__(16) int g_w1p[CMID * 24];   // [co][24 kwords]
__device__ __align__(16) int g_w2p[CMID * 3];    // [co][row]
__device__ __align__(16) int g_w3p[COUT * 144];  // [co][144 kwords]
__device__ __align__(16) signed char g_y1[B_ * CMID * HW_];
__device__ __align__(16) signed char g_y2[B_ * CMID * HW_];

// ---------------- prep: scales ----------------
__global__ void prep_scales(const float* __restrict__ r0, const float* __restrict__ r1,
                            const float* __restrict__ r2, const float* __restrict__ r3,
                            const int* __restrict__ cl, float* s3out) {
    int c = cl[0];
    g_s[0] = r0[c] / NBITF;
    g_s[1] = r1[c] / NBITF;
    g_s[2] = r2[c] / NBITF;
    float s3 = r3[c] / NBITF;
    g_s[3] = s3;
    if (s3out) *s3out = s3;
}

// ---------------- prep: BN fold + weight quant + packing ----------------
__global__ void __launch_bounds__(128) prep_weights(
    const float* __restrict__ w1, const float* __restrict__ g1, const float* __restrict__ b1,
    const float* __restrict__ m1, const float* __restrict__ v1,
    const float* __restrict__ w2, const float* __restrict__ g2, const float* __restrict__ b2,
    const float* __restrict__ m2, const float* __restrict__ v2,
    const float* __restrict__ w3, const float* __restrict__ g3, const float* __restrict__ b3,
    const float* __restrict__ m3, const float* __restrict__ v3) {
    __shared__ float sv[CMID];
    __shared__ signed char qs[CMID];
    __shared__ float red[128];
    int t = threadIdx.x;
    int bid = blockIdx.x;

    if (bid < CMID) {
        // ----- w1: [576, 96] -----
        int co = bid;
        float scale = g1[co] / sqrtf(v1[co] + 1e-5f);
        float v = 0.f;
        if (t < CIN) { v = w1[co * CIN + t] * scale; sv[t] = v; }
        red[t] = (t < CIN) ? fabsf(v) : 0.f;
        __syncthreads();
        for (int s = 64; s > 0; s >>= 1) { if (t < s) red[t] = fmaxf(red[t], red[t + s]); __syncthreads(); }
        float sc = red[0] / NBITF;
        if (t == 0) { g_ws1[co] = sc; g_bf1[co] = b1[co] - m1[co] * scale; }
        if (t < CIN) {
            float q = rintf(sv[t] / sc);
            q = fminf(fmaxf(q, -127.f), 127.f);
            qs[t] = (signed char)q;
        }
        __syncthreads();
        if (t < 24) {
            int w = (qs[4*t] & 0xFF) | ((qs[4*t+1] & 0xFF) << 8) |
                    ((qs[4*t+2] & 0xFF) << 16) | ((qs[4*t+3] & 0xFF) << 24);
            g_w1p[co * 24 + t] = w;
        }
    } else if (bid < 2 * CMID) {
        // ----- w2: [576, 9] depthwise -----
        int co = bid - CMID;
        float scale = g2[co] / sqrtf(v2[co] + 1e-5f);
        float v = 0.f;
        if (t < 9) { v = w2[co * 9 + t] * scale; sv[t] = v; }
        red[t] = (t < 9) ? fabsf(v) : 0.f;
        __syncthreads();
        for (int s = 64; s > 0; s >>= 1) { if (t < s) red[t] = fmaxf(red[t], red[t + s]); __syncthreads(); }
        float sc = red[0] / NBITF;
        if (t == 0) { g_ws2[co] = sc; g_bf2[co] = b2[co] - m2[co] * scale; }
        if (t < 9) {
            float q = rintf(sv[t] / sc);
            q = fminf(fmaxf(q, -127.f), 127.f);
            qs[t] = (signed char)q;
        }
        __syncthreads();
        if (t < 3) {
            int w = (qs[3*t] & 0xFF) | ((qs[3*t+1] & 0xFF) << 8) | ((qs[3*t+2] & 0xFF) << 16);
            g_w2p[co * 3 + t] = w;
        }
    } else {
        // ----- w3: [96, 576] -----
        int co = bid - 2 * CMID;
        float scale = g3[co] / sqrtf(v3[co] + 1e-5f);
        float lm = 0.f;
        for (int k = t; k < CMID; k += 128) {
            float v = w3[co * CMID + k] * scale;
            sv[k] = v;
            lm = fmaxf(lm, fabsf(v));
        }
        red[t] = lm;
        __syncthreads();
        for (int s = 64; s > 0; s >>= 1) { if (t < s) red[t] = fmaxf(red[t], red[t + s]); __syncthreads(); }
        float sc = red[0] / NBITF;
        if (t == 0) { g_ws3[co] = sc; g_bf3[co] = b3[co] - m3[co] * scale; }
        for (int k = t; k < CMID; k += 128) {
            float q = rintf(sv[k] / sc);
            q = fminf(fmaxf(q, -127.f), 127.f);
            qs[k] = (signed char)q;
        }
        __syncthreads();
        for (int p = t; p < 144; p += 128) {
            int w = (qs[4*p] & 0xFF) | ((qs[4*p+1] & 0xFF) << 8) |
                    ((qs[4*p+2] & 0xFF) << 16) | ((qs[4*p+3] & 0xFF) << 24);
            g_w3p[co * 144 + p] = w;
        }
    }
}

// ---------------- int8 tensor-core mma ----------------
__device__ __forceinline__ void mma_s8(int& d0, int& d1, int& d2, int& d3,
                                       int a0, int a1, int a2, int a3,
                                       int b0, int b1) {
    asm volatile(
        "mma.sync.aligned.m16n8k32.row.col.s32.s8.s8.s32 "
        "{%0,%1,%2,%3}, {%4,%5,%6,%7}, {%8,%9}, {%0,%1,%2,%3};"
        : "+r"(d0), "+r"(d1), "+r"(d2), "+r"(d3)
        : "r"(a0), "r"(a1), "r"(a2), "r"(a3), "r"(b0), "r"(b1));
}

// ---------------- k1: quant(x) + 1x1 conv (96->576) IMMA + ReLU6 + requant -> int8 ----------------
#define AS1 136   // a_sm row stride (words): banks (8*tg+g)%32 conflict-free
__global__ void __launch_bounds__(256) k1_conv1(const float* __restrict__ x) {
    __shared__ __align__(16) int a_sm[24 * AS1];     // [kword][128 px]   13056 B
    __shared__ __align__(16) int w_sm[192 * 28];     // [co_local][24+pad] 21504 B
    __shared__ float s_al[192], s_bb[192];
    __shared__ __align__(16) signed char o_sm[8 * 512];

    const int tid = threadIdx.x;
    const int n0 = blockIdx.x * 128;
    const float s0 = g_s[0];
    const float inv_s0 = 1.0f / s0;
    const float inv_s1 = 1.0f / g_s[1];

    // ---- quantize x tile (96ch x 128px) into k-packed smem ----
    for (int idx = tid; idx < 768; idx += 256) {        // 24 chgroups * 32 pxquads
        int cg = idx >> 5, q4 = idx & 31;
        int n = n0 + 4 * q4;
        int b = n / HW_;
        int hw = n - b * HW_;                            // 4px never cross image (784%4==0)
        int q[4][4];
        #pragma unroll
        for (int j = 0; j < 4; ++j) {
            float4 v = *(const float4*)(x + ((size_t)(b * CIN + 4 * cg + j) * HW_ + hw));
            float f;
            f = fminf(fmaxf(rintf(v.x * inv_s0), -127.f), 127.f); q[j][0] = (int)f;
            f = fminf(fmaxf(rintf(v.y * inv_s0), -127.f), 127.f); q[j][1] = (int)f;
            f = fminf(fmaxf(rintf(v.z * inv_s0), -127.f), 127.f); q[j][2] = (int)f;
            f = fminf(fmaxf(rintf(v.w * inv_s0), -127.f), 127.f); q[j][3] = (int)f;
        }
        int w[4];
        #pragma unroll
        for (int p = 0; p < 4; ++p) {
            int lo = __byte_perm(q[0][p], q[1][p], 0x0040);
            int hi = __byte_perm(q[2][p], q[3][p], 0x0040);
            w[p] = __byte_perm(lo, hi, 0x5410);
        }
        *(int4*)&a_sm[cg * AS1 + 4 * q4] = make_int4(w[0], w[1], w[2], w[3]);
    }

    const int lane = tid & 31, wid = tid >> 5;
    const int g = lane >> 2, tg = lane & 3;
    const int p0 = wid * 16;
    const int nn = n0 + p0;
    const int bw = nn / HW_;
    const int hww = nn - bw * HW_;                       // 16px tile never crosses (784%16==0)

    __syncthreads();

    // ---- per-warp A fragments (fixed px tile, all K=96) ----
    int A0[3], A1[3], A2[3], A3[3];
    #pragma unroll
    for (int s = 0; s < 3; ++s) {
        A0[s] = a_sm[(8 * s + tg) * AS1 + p0 + g];
        A1[s] = a_sm[(8 * s + tg) * AS1 + p0 + g + 8];
        A2[s] = a_sm[(8 * s + 4 + tg) * AS1 + p0 + g];
        A3[s] = a_sm[(8 * s + 4 + tg) * AS1 + p0 + g + 8];
    }

    for (int chunk = 0; chunk < 3; ++chunk) {
        __syncthreads();
        for (int idx = tid; idx < 1152; idx += 256) {    // 192 co * 6 int4
            int c = idx / 6, j = idx % 6;
            *(int4*)&w_sm[c * 28 + 4 * j] = *(const int4*)&g_w1p[(chunk * 192 + c) * 24 + 4 * j];
        }
        if (tid < 192) {
            int co = chunk * 192 + tid;
            s_al[tid] = s0 * g_ws1[co];
            s_bb[tid] = g_bf1[co];
        }
        __syncthreads();

        for (int ct = 0; ct < 24; ++ct) {
            const int co0 = ct * 8;
            int d0 = 0, d1 = 0, d2 = 0, d3 = 0;
            #pragma unroll
            for (int s = 0; s < 3; ++s) {
                int b0 = w_sm[(co0 + g) * 28 + 8 * s + tg];
                int b1 = w_sm[(co0 + g) * 28 + 8 * s + 4 + tg];
                mma_s8(d0, d1, d2, d3, A0[s], A1[s], A2[s], A3[s], b0, b1);
            }
            const int cA = co0 + 2 * tg, cB = cA + 1;
            const float alA = s_al[cA], bbA = s_bb[cA];
            const float alB = s_al[cB], bbB = s_bb[cB];
            signed char* ob = o_sm + wid * 512 + (ct & 3) * 128;
            float y; int q;
            y = fminf(fmaxf(fmaf((float)d0, alA, bbA), 0.f), 6.f);
            q = (int)rintf(y * inv_s1); q = q > 127 ? 127 : q;
            ob[(2 * tg) * 16 + g] = (signed char)q;
            y = fminf(fmaxf(fmaf((float)d1, alB, bbB), 0.f), 6.f);
            q = (int)rintf(y * inv_s1); q = q > 127 ? 127 : q;
            ob[(2 * tg + 1) * 16 + g] = (signed char)q;
            y = fminf(fmaxf(fmaf((float)d2, alA, bbA), 0.f), 6.f);
            q = (int)rintf(y * inv_s1); q = q > 127 ? 127 : q;
            ob[(2 * tg) * 16 + g + 8] = (signed char)q;
            y = fminf(fmaxf(fmaf((float)d3, alB, bbB), 0.f), 6.f);
            q = (int)rintf(y * inv_s1); q = q > 127 ? 127 : q;
            ob[(2 * tg + 1) * 16 + g + 8] = (signed char)q;

            if ((ct & 3) == 3) {
                __syncwarp();
                int4 v = *(const int4*)(o_sm + wid * 512 + lane * 16);
                int tb = lane >> 3, col = lane & 7;
                int cog = chunk * 192 + (ct - 3 + tb) * 8 + col;
                *(int4*)(g_y1 + (size_t)(bw * CMID + cog) * HW_ + hww) = v;
                __syncwarp();
            }
        }
    }
}

// ---------------- k2: depthwise 3x3 (int8) + ReLU6 + requant -> int8 (unchanged) ----------------
__global__ void __launch_bounds__(256) k2_dw() {
    int t = blockIdx.x * 256 + threadIdx.x;
    if (t >= B_ * CMID * 28) return;
    int h = t % 28;
    int bc = t / 28;
    int c = bc % CMID;
    int b = bc / CMID;
    int base = (b * CMID + c) * HW_;

    int r0[8], r1[8], r2[8];
    const int* p1 = (const int*)(g_y1 + base + h * 28);
    #pragma unroll
    for (int q = 0; q < 7; ++q) r1[q] = p1[q];
    r1[7] = 0;
    if (h > 0) {
        const int* p0 = p1 - 7;
        #pragma unroll
        for (int q = 0; q < 7; ++q) r0[q] = p0[q];
    } else {
        #pragma unroll
        for (int q = 0; q < 7; ++q) r0[q] = 0;
    }
    r0[7] = 0;
    if (h < 27) {
        const int* p2 = p1 + 7;
        #pragma unroll
        for (int q = 0; q < 7; ++q) r2[q] = p2[q];
    } else {
        #pragma unroll
        for (int q = 0; q < 7; ++q) r2[q] = 0;
    }
    r2[7] = 0;

    int wp0 = g_w2p[c * 3 + 0];
    int wp1 = g_w2p[c * 3 + 1];
    int wp2 = g_w2p[c * 3 + 2];
    float al = g_s[1] * g_ws2[c];
    float bb = g_bf2[c];
    float inv_s2 = 1.0f / g_s[2];

    unsigned int ow[7];
    #pragma unroll
    for (int q = 0; q < 7; ++q) ow[q] = 0u;

    #pragma unroll
    for (int w = 0; w < 28; ++w) {
        int op0, op1, op2;
        if (w == 0) {
            op0 = __byte_perm(r0[0], 0, 0x2104);
            op1 = __byte_perm(r1[0], 0, 0x2104);
            op2 = __byte_perm(r2[0], 0, 0x2104);
        } else {
            int s = w - 1, q = s >> 2, o = s & 3;
            unsigned sel = 0x3210u + (unsigned)o * 0x1111u;
            op0 = __byte_perm(r0[q], r0[q + 1], sel);
            op1 = __byte_perm(r1[q], r1[q + 1], sel);
            op2 = __byte_perm(r2[q], r2[q + 1], sel);
        }
        int acc = __dp4a(op0, wp0, __dp4a(op1, wp1, __dp4a(op2, wp2, 0)));
        float y = (float)acc * al + bb;
        y = fminf(fmaxf(y, 0.f), 6.f);
        int qv = (int)rintf(y * inv_s2);
        qv = qv > 127 ? 127 : qv;
        ow[w >> 2] |= (unsigned)(qv & 0xFF) << (8 * (w & 3));
    }
    int* po = (int*)(g_y2 + base + h * 28);
    #pragma unroll
    for (int q = 0; q < 7; ++q) po[q] = (int)ow[q];
}

// ---------------- k3: 1x1 conv (576->96) IMMA + bias + residual + final quant -> fp32 ----------------
#define AS3 136
#define WS3 52   // banks (20*g+tg)%32 conflict-free
__global__ void __launch_bounds__(256) k3_conv3(const float* __restrict__ x,
                                                float* __restrict__ out) {
    __shared__ __align__(16) int a_sm[48 * AS3];   // 26112 B
    __shared__ __align__(16) int w_sm[96 * WS3];   // 19968 B
    __shared__ float s_al[96], s_bb[96];

    const int tid = threadIdx.x, lane = tid & 31, wid = tid >> 5;
    const int g = lane >> 2, tg = lane & 3;
    const int n0 = blockIdx.x * 128;
    const int p0 = wid * 16;
    const int nn = n0 + p0;
    const int bw = nn / HW_;
    const int hww = nn - bw * HW_;

    int acc[12][4];
    #pragma unroll
    for (int nt = 0; nt < 12; ++nt)
        #pragma unroll
        for (int j = 0; j < 4; ++j) acc[nt][j] = 0;

    for (int chunk = 0; chunk < 3; ++chunk) {
        __syncthreads();
        // activations: 192ch x 128px, 4x4 byte-transpose into k-packed layout
        for (int idx = tid; idx < 1536; idx += 256) {
            int q4 = idx & 31, cg = idx >> 5;
            int n = n0 + 4 * q4;
            int b = n / HW_;
            int hw = n - b * HW_;
            const signed char* src = g_y2 + (size_t)(b * CMID + chunk * 192 + 4 * cg) * HW_ + hw;
            int r0 = *(const int*)(src);
            int r1 = *(const int*)(src + HW_);
            int r2 = *(const int*)(src + 2 * HW_);
            int r3 = *(const int*)(src + 3 * HW_);
            int t0 = __byte_perm(r0, r1, 0x5140), t1 = __byte_perm(r0, r1, 0x7362);
            int t2 = __byte_perm(r2, r3, 0x5140), t3 = __byte_perm(r2, r3, 0x7362);
            int o0 = __byte_perm(t0, t2, 0x5410), o1 = __byte_perm(t0, t2, 0x7632);
            int o2 = __byte_perm(t1, t3, 0x5410), o3 = __byte_perm(t1, t3, 0x7632);
            *(int4*)&a_sm[cg * AS3 + 4 * q4] = make_int4(o0, o1, o2, o3);
        }
        // weights chunk: 96 co x 48 words
        for (int idx = tid; idx < 1152; idx += 256) {
            int c = idx / 12, j = idx % 12;
            *(int4*)&w_sm[c * WS3 + 4 * j] = *(const int4*)&g_w3p[c * 144 + chunk * 48 + 4 * j];
        }
        if (chunk == 0 && tid < 96) {
            s_al[tid] = g_s[2] * g_ws3[tid];
            s_bb[tid] = g_bf3[tid];
        }
        __syncthreads();

        #pragma unroll
        for (int s = 0; s < 6; ++s) {
            int a0 = a_sm[(8 * s + tg) * AS3 + p0 + g];
            int a1 = a_sm[(8 * s + tg) * AS3 + p0 + g + 8];
            int a2 = a_sm[(8 * s + 4 + tg) * AS3 + p0 + g];
            int a3 = a_sm[(8 * s + 4 + tg) * AS3 + p0 + g + 8];
            #pragma unroll
            for (int nt = 0; nt < 12; ++nt) {
                int b0 = w_sm[(8 * nt + g) * WS3 + 8 * s + tg];
                int b1 = w_sm[(8 * nt + g) * WS3 + 8 * s + 4 + tg];
                mma_s8(acc[nt][0], acc[nt][1], acc[nt][2], acc[nt][3],
                       a0, a1, a2, a3, b0, b1);
            }
        }
    }

    const float s3 = g_s[3];
    const float inv_s3 = 1.0f / s3;
    #pragma unroll
    for (int nt = 0; nt < 12; ++nt) {
        const int cA = 8 * nt + 2 * tg, cB = cA + 1;
        const float alA = s_al[cA], bbA = s_bb[cA];
        const float alB = s_al[cB], bbB = s_bb[cB];
        size_t oA = (size_t)(bw * COUT + cA) * HW_ + hww + g;
        size_t oB = (size_t)(bw * COUT + cB) * HW_ + hww + g;
        float y, q;
        y = fmaf((float)acc[nt][0], alA, bbA) + x[oA];
        q = fminf(fmaxf(rintf(y * inv_s3), -127.f), 127.f);
        out[oA] = q * s3;
        y = fmaf((float)acc[nt][1], alB, bbB) + x[oB];
        q = fminf(fmaxf(rintf(y * inv_s3), -127.f), 127.f);
        out[oB] = q * s3;
        y = fmaf((float)acc[nt][2], alA, bbA) + x[oA + 8];
        q = fminf(fmaxf(rintf(y * inv_s3), -127.f), 127.f);
        out[oA + 8] = q * s3;
        y = fmaf((float)acc[nt][3], alB, bbB) + x[oB + 8];
        q = fminf(fmaxf(rintf(y * inv_s3), -127.f), 127.f);
        out[oB + 8] = q * s3;
    }
}

// ---------------- launch ----------------
extern "C" void kernel_launch(void* const* d_in, const int* in_sizes, int n_in,
                              void* d_out, int out_size) {
    const float* x  = (const float*)d_in[0];
    const float* w1 = (const float*)d_in[1];
    const float* g1 = (const float*)d_in[2];
    const float* b1 = (const float*)d_in[3];
    const float* m1 = (const float*)d_in[4];
    const float* v1 = (const float*)d_in[5];
    const float* w2 = (const float*)d_in[6];
    const float* g2 = (const float*)d_in[7];
    const float* b2 = (const float*)d_in[8];
    const float* m2 = (const float*)d_in[9];
    const float* v2 = (const float*)d_in[10];
    const float* w3 = (const float*)d_in[11];
    const float* g3 = (const float*)d_in[12];
    const float* b3 = (const float*)d_in[13];
    const float* m3 = (const float*)d_in[14];
    const float* v3 = (const float*)d_in[15];
    const float* r0 = (const float*)d_in[16];
    const float* r1 = (const float*)d_in[17];
    const float* r2 = (const float*)d_in[18];
    const float* r3 = (const float*)d_in[19];
    const int*   cl = (const int*)d_in[20];

    float* out = (float*)d_out;
    const int NOUT = B_ * COUT * HW_;
    float* s3out = (out_size > NOUT) ? out + NOUT : nullptr;

    prep_scales<<<1, 1>>>(r0, r1, r2, r3, cl, s3out);
    prep_weights<<<2 * CMID + COUT, 128>>>(w1, g1, b1, m1, v1,
                                           w2, g2, b2, m2, v2,
                                           w3, g3, b3, m3, v3);
    k1_conv1<<<NPIX / 128, 256>>>(x);
    k2_dw<<<(B_ * CMID * 28 + 255) / 256, 256>>>();
    k3_conv3<<<NPIX / 128, 256>>>(x, out);
}